// round 6
// baseline (speedup 1.0000x reference)
#include <cuda_runtime.h>
#include <cstdint>
#include <cstddef>

#define BB  8
#define CC  256
#define NQ  4096
#define NK  4096
#define KNN 8

// Scratch (device globals; no runtime allocation allowed)
__device__ int   g_idx[(size_t)BB * NQ * KNN];            // 1 MiB
__device__ float g_kft[(size_t)BB * NK * CC];             // 32 MiB, (B, NK, C)

// ---------------------------------------------------------------------------
// 1) Brute-force KNN. Arithmetic EXACTLY mirrors the XLA lowering (verified
//    rel_err == 0.0): do not touch the __f*_rn sequence.
//    Top-8 sorted ascending in registers; strict '<' insertion preserves
//    lax.top_k tie stability.
// ---------------------------------------------------------------------------
__global__ void knn_kernel(const float* __restrict__ qc,
                           const float* __restrict__ kc) {
    extern __shared__ float4 s_key[];                     // NK * 16B = 64 KiB
    const int b  = blockIdx.x >> 4;                       // 16 tiles per batch
    const int qt = blockIdx.x & 15;
    const int q  = qt * 256 + threadIdx.x;

    const float* kcb = kc + (size_t)b * 3 * NK;
    for (int i = threadIdx.x; i < NK; i += 256) {
        float kx = kcb[i], ky = kcb[NK + i], kz = kcb[2 * NK + i];
        float kk = __fadd_rn(__fadd_rn(__fmul_rn(kx, kx), __fmul_rn(ky, ky)),
                             __fmul_rn(kz, kz));
        s_key[i] = make_float4(kx, ky, kz, kk);
    }
    __syncthreads();

    const float* qcb = qc + (size_t)b * 3 * NQ;
    const float qx = qcb[q], qy = qcb[NQ + q], qz = qcb[2 * NQ + q];
    const float qq = __fadd_rn(__fadd_rn(__fmul_rn(qx, qx), __fmul_rn(qy, qy)),
                               __fmul_rn(qz, qz));

    float bd[KNN];
    int   bi[KNN];
#pragma unroll
    for (int k = 0; k < KNN; k++) { bd[k] = 3.402823466e38f; bi[k] = 0; }

#pragma unroll 8
    for (int j = 0; j < NK; j++) {
        float4 s  = s_key[j];
        float dot = __fmul_rn(qx, s.x);
        dot = __fmaf_rn(qy, s.y, dot);
        dot = __fmaf_rn(qz, s.z, dot);
        float d = __fadd_rn(__fsub_rn(qq, __fmul_rn(2.0f, dot)), s.w);
        if (d < bd[KNN - 1]) {
            bd[KNN - 1] = d; bi[KNN - 1] = j;
#pragma unroll
            for (int k = KNN - 1; k > 0; k--) {
                if (bd[k] < bd[k - 1]) {                  // strict: stable for ties
                    float td = bd[k]; bd[k] = bd[k - 1]; bd[k - 1] = td;
                    int   ti = bi[k]; bi[k] = bi[k - 1]; bi[k - 1] = ti;
                }
            }
        }
    }

    int* op = g_idx + ((size_t)b * NQ + q) * KNN;
#pragma unroll
    for (int k = 0; k < KNN; k++) op[k] = bi[k];
}

// ---------------------------------------------------------------------------
// 2) Transpose key_features (B, C, NK) -> (B, NK, C) so neighbor rows are
//    contiguous 1 KiB segments for the gather.
// ---------------------------------------------------------------------------
__global__ void transpose_kernel(const float* __restrict__ kf) {
    __shared__ float tile[32][33];
    const int b  = blockIdx.z;
    const int n0 = blockIdx.x * 32;
    const int c0 = blockIdx.y * 32;
    const float* src = kf + (size_t)b * CC * NK;
#pragma unroll
    for (int i = 0; i < 4; i++) {
        int c = c0 + threadIdx.y + i * 8;
        tile[threadIdx.y + i * 8][threadIdx.x] = src[(size_t)c * NK + n0 + threadIdx.x];
    }
    __syncthreads();
    float* dst = g_kft + (size_t)b * NK * CC;
#pragma unroll
    for (int i = 0; i < 4; i++) {
        int n = n0 + threadIdx.y + i * 8;
        dst[(size_t)n * CC + c0 + threadIdx.x] = tile[threadIdx.x][threadIdx.y + i * 8];
    }
}

// ---------------------------------------------------------------------------
// 3) Fused output kernel: writes BOTH halves.
//      lower: out[b, c,    q, k] = kf[b, c, idx[q,k]] - qf[b, c, q]
//      upper: out[b, C+c,  q, k] = qf[b, c, q]
//    Block = 32 queries (256 slots), chunking 32 channels at a time.
//    SMEM layout addr(q,k,c) = (33*k + q)*33 + c  — bank-conflict-free for:
//      fill STS.32  (bank = (l>>3)+4(l&7)+const, all distinct)
//      read  LDS.32 (bank = l + const, all distinct)
//    Stores are STG.128 (float4 along k).
// ---------------------------------------------------------------------------
__global__ void gather_kernel(const float* __restrict__ qf,
                              float* __restrict__ out) {
    __shared__ float s_nb[8704];                          // (33*7+31)*33+32 < 8704
    __shared__ float qsm[32 * 33];
    __shared__ int   s_idx[256];

    const int b  = blockIdx.x >> 7;                       // 128 tiles per batch
    const int qt = blockIdx.x & 127;
    const int q0 = qt * 32;
    const int t  = threadIdx.x;

    s_idx[t] = g_idx[((size_t)b * NQ + q0) * KNN + t];
    __syncthreads();

    const float* kftb = g_kft + (size_t)b * NK * CC;
    const float* qfb  = qf + (size_t)b * CC * NQ;

    // write-phase decomposition
    const int q  = t & 31;           // lane -> query (coalesced stores)
    const int hf = (t >> 5) & 1;     // k half: 0 -> k0..3, 1 -> k4..7
    const int cg = t >> 6;           // channel group 0..3

    for (int c0 = 0; c0 < CC; c0 += 32) {
        // ---- fill neighbor tile ----
#pragma unroll
        for (int rr = 0; rr < 8; rr++) {
            int s = rr * 32 + (t >> 3);                   // slot = q*8 + k
            int n = s_idx[s];
            float4 v = ((const float4*)(kftb + (size_t)n * CC + c0))[t & 7];
            int sq = s >> 3, sk = s & 7;
            int base = (33 * sk + sq) * 33 + (t & 7) * 4;
            s_nb[base + 0] = v.x; s_nb[base + 1] = v.y;
            s_nb[base + 2] = v.z; s_nb[base + 3] = v.w;
        }
        // ---- fill query tile ----
#pragma unroll
        for (int rr = 0; rr < 4; rr++) {
            int i = rr * 8 + (t >> 5);
            qsm[i * 33 + (t & 31)] = qfb[(size_t)(c0 + i) * NQ + q0 + (t & 31)];
        }
        __syncthreads();

        // ---- write both halves, float4 along k ----
        float* lowb = out + ((size_t)b * 2 * CC + c0) * NQ * KNN + (size_t)q0 * KNN;
        float* upb  = lowb + (size_t)CC * NQ * KNN;
#pragma unroll
        for (int r = 0; r < 8; r++) {
            int c = cg + 4 * r;
            float qv = qsm[c * 33 + q];
            float4 o;
            o.x = s_nb[(33 * (hf * 4 + 0) + q) * 33 + c] - qv;
            o.y = s_nb[(33 * (hf * 4 + 1) + q) * 33 + c] - qv;
            o.z = s_nb[(33 * (hf * 4 + 2) + q) * 33 + c] - qv;
            o.w = s_nb[(33 * (hf * 4 + 3) + q) * 33 + c] - qv;
            size_t co = (size_t)c * (NQ * KNN) + q * 8 + hf * 4;
            *(float4*)(lowb + co) = o;
            *(float4*)(upb  + co) = make_float4(qv, qv, qv, qv);
        }
        __syncthreads();
    }
}

// ---------------------------------------------------------------------------
extern "C" void kernel_launch(void* const* d_in, const int* in_sizes, int n_in,
                              void* d_out, int out_size) {
    const float* query_coords   = (const float*)d_in[0];
    const float* query_features = (const float*)d_in[1];
    const float* key_coords     = (const float*)d_in[2];
    const float* key_features   = (const float*)d_in[3];
    float* out = (float*)d_out;
    (void)in_sizes; (void)n_in; (void)out_size;

    cudaFuncSetAttribute(knn_kernel,
                         cudaFuncAttributeMaxDynamicSharedMemorySize, NK * 16);

    knn_kernel<<<BB * (NQ / 256), 256, NK * 16>>>(query_coords, key_coords);
    transpose_kernel<<<dim3(NK / 32, CC / 32, BB), dim3(32, 8)>>>(key_features);
    gather_kernel<<<BB * (NQ / 32), 256>>>(query_features, out);
}